// round 14
// baseline (speedup 1.0000x reference)
#include <cuda_runtime.h>
#include <cuda_bf16.h>
#include <cstdint>

// ---------------------------------------------------------------------------
// YOLOv2 decode + greedy per-class NMS (exact sorted-walk equivalence).
// R14: = R13-best, but the 4096-bin score histogram is built in decode via
//      global atomics (amortized over 4000 CTAs) instead of ~8000 serialized
//      shared-memory atomics inside the 64-CTA nms kernel.
// ---------------------------------------------------------------------------

static constexpr int Bn = 64;
static constexpr int Hn = 40;
static constexpr int Wn = 40;
static constexpr int An = 5;
static constexpr int Cn = 80;
static constexpr int NPB = Hn * Wn * An;      // 8000
static constexpr int NBOX = Bn * NPB;         // 512000
static constexpr int MAXB = 100;
static constexpr int NBIN = 4096;             // fine bins: (key>>36) - (117<<8)
static constexpr int BINBASE = 117 << 8;
static constexpr int TARGET = 256;
static constexpr int MCAP = 512;
static constexpr float SCORE_THR = 0.001f;
static constexpr float IOU_THR = 0.5f;

__device__ unsigned long long g_keys[NBOX];
__device__ unsigned int g_hist[Bn * NBIN];    // zero at load; nms re-zeroes

// ---------------------------------------------------------------------------
// Decode: 512 thr/block, four threads per box; writes keys + global histogram.
// ---------------------------------------------------------------------------
__global__ __launch_bounds__(512, 4) void decode_kernel(
    const float* __restrict__ pred)
{
    __shared__ __align__(16) float s[128 * 85];
    const int tid = threadIdx.x;
    const unsigned FULL = 0xffffffffu;

    {
        const float4* src = (const float4*)pred + (long long)blockIdx.x * 2720;
        float4* dst = (float4*)s;
        #pragma unroll
        for (int i = 0; i < 5; ++i)
            dst[tid + i * 512] = src[tid + i * 512];
        if (tid < 160) dst[tid + 2560] = src[tid + 2560];
    }
    __syncthreads();

    const int boxl = tid >> 2;
    const int q    = tid & 3;
    const float* p = s + boxl * 85;
    const int jb = 5 + q * 20;

    float bv = p[jb];
    int   bc = jb - 5;
    #pragma unroll 4
    for (int j = jb + 1; j < jb + 20; ++j) {
        float v = p[j];
        if (v > bv) { bv = v; bc = j - 5; }
    }
    #pragma unroll
    for (int o = 1; o <= 2; o <<= 1) {
        float obv = __shfl_xor_sync(FULL, bv, o);
        int   obc = __shfl_xor_sync(FULL, bc, o);
        if (obv > bv || (obv == bv && obc < bc)) { bv = obv; bc = obc; }
    }

    float a0 = 0.f, a1 = 0.f;
    #pragma unroll 4
    for (int j = jb; j < jb + 20; j += 2) {
        a0 += expf(p[j]     - bv);
        a1 += expf(p[j + 1] - bv);
    }
    float se = a0 + a1;
    #pragma unroll
    for (int o = 1; o <= 2; o <<= 1)
        se += __shfl_xor_sync(FULL, se, o);

    if (q == 0) {
        const int box = blockIdx.x * 128 + boxl;
        const int n   = box % NPB;
        const int b   = box / NPB;
        float conf  = 1.0f / (1.0f + expf(-p[4]));
        float score = conf / se;

        unsigned long long key = 0ull;
        if (score > SCORE_THR) {
            key = ((unsigned long long)__float_as_uint(score) << 21)
                | ((unsigned long long)(unsigned)(8191 - n) << 8)
                | (unsigned long long)(unsigned)bc;
            atomicAdd(&g_hist[b * NBIN + ((int)(key >> 36) - BINBASE)], 1u);
        }
        g_keys[box] = key;
    }
}

__device__ __forceinline__ float iou_(float4 a, float4 b) {
    float xx1 = fmaxf(a.x, b.x), yy1 = fmaxf(a.y, b.y);
    float xx2 = fminf(a.z, b.z), yy2 = fminf(a.w, b.w);
    float inter = fmaxf(xx2 - xx1, 0.0f) * fmaxf(yy2 - yy1, 0.0f);
    float aa = fmaxf(a.z - a.x, 0.0f) * fmaxf(a.w - a.y, 0.0f);
    float ab = fmaxf(b.z - b.x, 0.0f) * fmaxf(b.w - b.y, 0.0f);
    return inter / (aa + ab - inter + 1e-8f);
}

__device__ __forceinline__ float4 decode_box_(
    const float* __restrict__ pred, const float* __restrict__ anch,
    int b, int n)
{
    const float* pp = pred + ((long long)b * NPB + n) * 85;
    float t0 = pp[0], t1 = pp[1], t2 = pp[2], t3 = pp[3];
    int a  = n % An;
    int hw = n / An;
    float gy = (float)(hw / Wn);
    float gx = (float)(hw % Wn);
    float sx = 1.0f / (1.0f + expf(-t0));
    float sy = 1.0f / (1.0f + expf(-t1));
    float cx = (sx + gx) / 40.0f;
    float cy = (sy + gy) / 40.0f;
    float bw = (expf(t2) * anch[2 * a])     / 40.0f;
    float bh = (expf(t3) * anch[2 * a + 1]) / 40.0f;
    return make_float4(cx - 0.5f * bw, cy - 0.5f * bh,
                       cx + 0.5f * bw, cy + 0.5f * bh);
}

// ---------------------------------------------------------------------------
// NMS: hist from gmem (built by decode) -> scan -> window select -> compact
// from register keys -> rank-sort -> class-decomposed greedy -> output.
// dyn smem: buf u64[8192] 64KB | buf2 u64[8192] 64KB | sbox f4[512] 8KB
// ---------------------------------------------------------------------------
static constexpr int SMEM_NMS = 8192 * 8 * 2 + MCAP * 16;   // 136 KB

__global__ __launch_bounds__(1024, 1) void nms_kernel(
    float* __restrict__ out,
    const float* __restrict__ pred, const float* __restrict__ anch)
{
    extern __shared__ unsigned char smraw[];
    unsigned long long* buf  = (unsigned long long*)smraw;
    unsigned long long* buf2 = buf + 8192;
    float4*             sbox = (float4*)(buf2 + 8192);

    __shared__ unsigned hist[NBIN];
    __shared__ float4 abox[MAXB];
    __shared__ int    acls[MAXB];
    __shared__ unsigned sbm[MCAP / 32];
    __shared__ unsigned wsum[32], wsufex[32];
    __shared__ int    sh_count, sh_pos, sh_binLo, sh_prevLo, sh_consumed;
    __shared__ int    sh_overflow;

    const int b    = blockIdx.x;
    const int tid  = threadIdx.x;
    const int lane = tid & 31;
    const int wid  = tid >> 5;
    const unsigned FULL = 0xffffffffu;

    // hist from gmem (built by decode) + re-zero for next replay
    #pragma unroll
    for (int t = tid; t < NBIN; t += 1024) {
        hist[t] = g_hist[b * NBIN + t];
        g_hist[b * NBIN + t] = 0u;
    }
    if (tid == 0) { sh_count = 0; sh_consumed = 0; sh_prevLo = NBIN; }

    // load keys into registers (8/thread) — no histogram work needed
    unsigned long long k[8];
    int kb[8];
    #pragma unroll
    for (int j = 0; j < 8; ++j) {
        int idx = tid + j * 1024;
        k[j] = (idx < NPB) ? g_keys[b * NPB + idx] : 0ull;
        kb[j] = (int)(k[j] >> 36) - BINBASE;
    }
    __syncthreads();

    {   // hierarchical suffix scan over 4096 bins
        unsigned h0 = hist[4 * tid + 0], h1 = hist[4 * tid + 1];
        unsigned h2 = hist[4 * tid + 2], h3 = hist[4 * tid + 3];
        unsigned s3 = h3, s2 = h2 + s3, s1 = h1 + s2, s0 = h0 + s1;
        unsigned gs = s0;
        unsigned suf = gs;
        #pragma unroll
        for (int o = 1; o < 32; o <<= 1) {
            unsigned v = __shfl_down_sync(FULL, suf, o);
            if (lane + o < 32) suf += v;
        }
        if (lane == 0) wsum[wid] = suf;
        __syncthreads();
        if (wid == 0) {
            unsigned ws = wsum[lane];
            unsigned sw = ws;
            #pragma unroll
            for (int o = 1; o < 32; o <<= 1) {
                unsigned v = __shfl_down_sync(FULL, sw, o);
                if (lane + o < 32) sw += v;
            }
            wsufex[lane] = sw - ws;
        }
        __syncthreads();
        unsigned above = wsufex[wid] + (suf - gs);
        hist[4 * tid + 0] = s0 + above;
        hist[4 * tid + 1] = s1 + above;
        hist[4 * tid + 2] = s2 + above;
        hist[4 * tid + 3] = s3 + above;
    }
    __syncthreads();

    const int total = (int)hist[0];

    float* out_boxes = out;
    float* out_score = out + (long long)Bn * MAXB * 4;
    float* out_class = out + (long long)Bn * MAXB * 5;

    bool first_chunk = true;

    while (true) {
        __syncthreads();
        int count    = sh_count;
        int consumed = sh_consumed;
        int prevLo   = sh_prevLo;
        if (count >= MAXB || consumed >= total) break;

        if (tid == 0) { sh_binLo = 0; sh_pos = 0; sh_overflow = 0; }
        __syncthreads();

        {
            int best = 0;
            for (int t = tid; t < prevLo; t += 1024)
                if ((int)hist[t] - consumed >= TARGET) best = max(best, t);
            best = (int)__reduce_max_sync(FULL, (unsigned)best);
            if (lane == 0 && best) atomicMax(&sh_binLo, best);
        }
        __syncthreads();
        int binLo = sh_binLo;

        #pragma unroll
        for (int j = 0; j < 8; ++j) {
            bool take = (k[j] != 0ull) && (kb[j] >= binLo) && (kb[j] < prevLo);
            unsigned msk = __ballot_sync(FULL, take);
            int base = 0;
            if (lane == 0 && msk) base = atomicAdd(&sh_pos, __popc(msk));
            base = __shfl_sync(FULL, base, 0);
            if (take)
                buf[base + __popc(msk & ((1u << lane) - 1u))] = k[j];
        }
        __syncthreads();
        int cnt = sh_pos;
        if (tid == 0) { sh_consumed = consumed + cnt; sh_prevLo = binLo; }
        __syncthreads();

        for (int i = tid; i < cnt; i += 1024) {
            unsigned long long ki = buf[i];
            int r = 0;
            for (int j = 0; j < cnt; ++j)
                r += (buf[j] > ki);
            buf2[r] = ki;
        }
        __syncthreads();

        int walk_start = 0;

        if (first_chunk) {
            int M = min(cnt, MCAP);

            if (tid < M) {
                unsigned long long kk = buf2[tid];
                int n = 8191 - (int)((kk >> 8) & 0x1FFFu);
                sbox[tid] = decode_box_(pred, anch, b, n);
            }
            if (tid < MCAP / 32) sbm[tid] = 0u;
            __syncthreads();

            for (int c = wid; c < Cn; c += 32) {
                float4 acc0, acc1;
                int na = 0;
                for (int base = 0; base < M; base += 32) {
                    int i = base + lane;
                    bool mine = (i < M) && ((int)(buf2[i] & 0xFFu) == c);
                    unsigned mk = __ballot_sync(FULL, mine);
                    while (mk) {
                        int i2 = base + (__ffs(mk) - 1);
                        mk &= mk - 1;
                        float4 bx = sbox[i2];
                        bool hit = false;
                        if (lane < na)      hit  = iou_(acc0, bx) > IOU_THR;
                        if (32 + lane < na) hit |= iou_(acc1, bx) > IOU_THR;
                        if (!__any_sync(FULL, hit)) {
                            if (na < 64) {
                                if (lane == (na & 31)) {
                                    if (na < 32) acc0 = bx; else acc1 = bx;
                                }
                                if (lane == 0)
                                    atomicOr(&sbm[i2 >> 5], 1u << (i2 & 31));
                            } else {
                                if (lane == 0) sh_overflow = 1;
                            }
                            ++na;
                        }
                    }
                }
            }
            __syncthreads();

            if (!sh_overflow) {
                if (tid < 32) {
                    int c = 0;
                    for (int w = 0; w < MCAP / 32 && c < MAXB; ++w) {
                        unsigned bits = sbm[w];
                        bool set = (bits >> lane) & 1u;
                        int rank = __popc(bits & ((1u << lane) - 1u));
                        int slot = c + rank;
                        if (set && slot < MAXB) {
                            int i2 = w * 32 + lane;
                            unsigned long long key = buf2[i2];
                            float4 bx = sbox[i2];
                            abox[slot] = bx;
                            acls[slot] = (int)(key & 0xFFu);
                            long long o = (long long)b * MAXB + slot;
                            out_boxes[o * 4 + 0] = bx.x;
                            out_boxes[o * 4 + 1] = bx.y;
                            out_boxes[o * 4 + 2] = bx.z;
                            out_boxes[o * 4 + 3] = bx.w;
                            out_score[o] = __uint_as_float((unsigned)(key >> 21));
                            out_class[o] = (float)(key & 0xFFu);
                        }
                        c = min(c + __popc(bits), MAXB);
                    }
                    if (lane == 0) sh_count = c;
                }
                walk_start = M;
            } else {
                walk_start = 0;
            }
            __syncthreads();
            first_chunk = false;
            if (sh_count >= MAXB || walk_start >= cnt) continue;
        }

        for (int base = walk_start; base < cnt; base += MCAP) {
            __syncthreads();
            if (sh_count >= MAXB) break;
            int mm = min(MCAP, cnt - base);

            if (tid < mm) {
                unsigned long long kk = buf2[base + tid];
                int n = 8191 - (int)((kk >> 8) & 0x1FFFu);
                sbox[tid] = decode_box_(pred, anch, b, n);
            }
            __syncthreads();

            if (tid < 32) {
                int c = sh_count;
                for (int ii = 0; ii < mm && c < MAXB; ++ii) {
                    unsigned long long key = buf2[base + ii];
                    int cls = (int)(key & 0xFFu);
                    float4 bx = sbox[ii];
                    bool rej = false;
                    for (int j = lane; j < c; j += 32) {
                        if (acls[j] == cls && iou_(abox[j], bx) > IOU_THR)
                            rej = true;
                    }
                    if (!__any_sync(FULL, rej)) {
                        if (lane == 0) {
                            abox[c] = bx;
                            acls[c] = cls;
                            long long o = (long long)b * MAXB + c;
                            out_boxes[o * 4 + 0] = bx.x;
                            out_boxes[o * 4 + 1] = bx.y;
                            out_boxes[o * 4 + 2] = bx.z;
                            out_boxes[o * 4 + 3] = bx.w;
                            out_score[o] = __uint_as_float((unsigned)(key >> 21));
                            out_class[o] = (float)cls;
                        }
                        __syncwarp();
                        ++c;
                    }
                }
                if (lane == 0) sh_count = c;
            }
        }
    }
    __syncthreads();

    int cnt = sh_count;
    for (int j = tid; j < MAXB; j += 1024) {
        if (j >= cnt) {
            long long o = (long long)b * MAXB + j;
            out_boxes[o * 4 + 0] = 0.0f;
            out_boxes[o * 4 + 1] = 0.0f;
            out_boxes[o * 4 + 2] = 0.0f;
            out_boxes[o * 4 + 3] = 0.0f;
            out_score[o] = 0.0f;
            out_class[o] = -1.0f;
        }
    }
}

extern "C" void kernel_launch(void* const* d_in, const int* in_sizes, int n_in,
                              void* d_out, int out_size)
{
    const float* pred = (const float*)d_in[0];
    const float* anch = (const float*)d_in[1];
    float* out = (float*)d_out;

    cudaFuncSetAttribute(nms_kernel,
                         cudaFuncAttributeMaxDynamicSharedMemorySize, SMEM_NMS);

    decode_kernel<<<NBOX / 128, 512>>>(pred);
    nms_kernel<<<Bn, 1024, SMEM_NMS>>>(out, pred, anch);
}

// round 15
// speedup vs baseline: 1.0913x; 1.0913x over previous
#include <cuda_runtime.h>
#include <cuda_bf16.h>
#include <cstdint>

// ---------------------------------------------------------------------------
// YOLOv2 decode + greedy per-class NMS (exact sorted-walk equivalence).
// R15: = R13-best (hist built in nms via smem atomics), with nms shrunk to
//      512 threads (halved barrier/arbiter cost) and TARGET 256->128
//      (halved candidate window -> smaller sort+walk).
// ---------------------------------------------------------------------------

static constexpr int Bn = 64;
static constexpr int Hn = 40;
static constexpr int Wn = 40;
static constexpr int An = 5;
static constexpr int Cn = 80;
static constexpr int NPB = Hn * Wn * An;      // 8000
static constexpr int NBOX = Bn * NPB;         // 512000
static constexpr int MAXB = 100;
static constexpr int NBIN = 4096;             // fine bins: (key>>36) - (117<<8)
static constexpr int BINBASE = 117 << 8;
static constexpr int TARGET = 128;
static constexpr int MCAP = 512;
static constexpr int NTN = 512;               // nms block size
static constexpr float SCORE_THR = 0.001f;
static constexpr float IOU_THR = 0.5f;

__device__ unsigned long long g_keys[NBOX];

// ---------------------------------------------------------------------------
// Decode: identical to R13-best. 512 thr/block, four threads per box.
// ---------------------------------------------------------------------------
__global__ __launch_bounds__(512, 4) void decode_kernel(
    const float* __restrict__ pred)
{
    __shared__ __align__(16) float s[128 * 85];
    const int tid = threadIdx.x;
    const unsigned FULL = 0xffffffffu;

    {
        const float4* src = (const float4*)pred + (long long)blockIdx.x * 2720;
        float4* dst = (float4*)s;
        #pragma unroll
        for (int i = 0; i < 5; ++i)
            dst[tid + i * 512] = src[tid + i * 512];
        if (tid < 160) dst[tid + 2560] = src[tid + 2560];
    }
    __syncthreads();

    const int boxl = tid >> 2;
    const int q    = tid & 3;
    const float* p = s + boxl * 85;
    const int jb = 5 + q * 20;

    float bv = p[jb];
    int   bc = jb - 5;
    #pragma unroll 4
    for (int j = jb + 1; j < jb + 20; ++j) {
        float v = p[j];
        if (v > bv) { bv = v; bc = j - 5; }
    }
    #pragma unroll
    for (int o = 1; o <= 2; o <<= 1) {
        float obv = __shfl_xor_sync(FULL, bv, o);
        int   obc = __shfl_xor_sync(FULL, bc, o);
        if (obv > bv || (obv == bv && obc < bc)) { bv = obv; bc = obc; }
    }

    float a0 = 0.f, a1 = 0.f;
    #pragma unroll 4
    for (int j = jb; j < jb + 20; j += 2) {
        a0 += expf(p[j]     - bv);
        a1 += expf(p[j + 1] - bv);
    }
    float se = a0 + a1;
    #pragma unroll
    for (int o = 1; o <= 2; o <<= 1)
        se += __shfl_xor_sync(FULL, se, o);

    if (q == 0) {
        const int box = blockIdx.x * 128 + boxl;
        const int n   = box % NPB;
        float conf  = 1.0f / (1.0f + expf(-p[4]));
        float score = conf / se;

        unsigned long long key = 0ull;
        if (score > SCORE_THR) {
            key = ((unsigned long long)__float_as_uint(score) << 21)
                | ((unsigned long long)(unsigned)(8191 - n) << 8)
                | (unsigned long long)(unsigned)bc;
        }
        g_keys[box] = key;
    }
}

__device__ __forceinline__ float iou_(float4 a, float4 b) {
    float xx1 = fmaxf(a.x, b.x), yy1 = fmaxf(a.y, b.y);
    float xx2 = fminf(a.z, b.z), yy2 = fminf(a.w, b.w);
    float inter = fmaxf(xx2 - xx1, 0.0f) * fmaxf(yy2 - yy1, 0.0f);
    float aa = fmaxf(a.z - a.x, 0.0f) * fmaxf(a.w - a.y, 0.0f);
    float ab = fmaxf(b.z - b.x, 0.0f) * fmaxf(b.w - b.y, 0.0f);
    return inter / (aa + ab - inter + 1e-8f);
}

__device__ __forceinline__ float4 decode_box_(
    const float* __restrict__ pred, const float* __restrict__ anch,
    int b, int n)
{
    const float* pp = pred + ((long long)b * NPB + n) * 85;
    float t0 = pp[0], t1 = pp[1], t2 = pp[2], t3 = pp[3];
    int a  = n % An;
    int hw = n / An;
    float gy = (float)(hw / Wn);
    float gx = (float)(hw % Wn);
    float sx = 1.0f / (1.0f + expf(-t0));
    float sy = 1.0f / (1.0f + expf(-t1));
    float cx = (sx + gx) / 40.0f;
    float cy = (sy + gy) / 40.0f;
    float bw = (expf(t2) * anch[2 * a])     / 40.0f;
    float bh = (expf(t3) * anch[2 * a + 1]) / 40.0f;
    return make_float4(cx - 0.5f * bw, cy - 0.5f * bh,
                       cx + 0.5f * bw, cy + 0.5f * bh);
}

// ---------------------------------------------------------------------------
// NMS: 512 threads/CTA. smem-atomic hist -> scan (8 bins/thread, 16 warps)
// -> window select -> register compact -> rank-sort -> class walk -> output.
// dyn smem: buf u64[8192] 64KB | buf2 u64[8192] 64KB | sbox f4[512] 8KB
// ---------------------------------------------------------------------------
static constexpr int SMEM_NMS = 8192 * 8 * 2 + MCAP * 16;   // 136 KB

__global__ __launch_bounds__(NTN, 1) void nms_kernel(
    float* __restrict__ out,
    const float* __restrict__ pred, const float* __restrict__ anch)
{
    extern __shared__ unsigned char smraw[];
    unsigned long long* buf  = (unsigned long long*)smraw;
    unsigned long long* buf2 = buf + 8192;
    float4*             sbox = (float4*)(buf2 + 8192);

    __shared__ unsigned hist[NBIN];
    __shared__ float4 abox[MAXB];
    __shared__ int    acls[MAXB];
    __shared__ unsigned sbm[MCAP / 32];
    __shared__ unsigned wsum[16], wsufex[16];
    __shared__ int    sh_count, sh_pos, sh_binLo, sh_prevLo, sh_consumed;
    __shared__ int    sh_overflow;

    const int b    = blockIdx.x;
    const int tid  = threadIdx.x;
    const int lane = tid & 31;
    const int wid  = tid >> 5;
    const unsigned FULL = 0xffffffffu;

    #pragma unroll
    for (int t = tid; t < NBIN; t += NTN) hist[t] = 0u;
    if (tid == 0) { sh_count = 0; sh_consumed = 0; sh_prevLo = NBIN; }
    __syncthreads();

    // load keys into registers (16/thread) + smem histogram
    unsigned long long k[16];
    #pragma unroll
    for (int j = 0; j < 16; ++j) {
        int idx = tid + j * NTN;
        k[j] = (idx < NPB) ? g_keys[b * NPB + idx] : 0ull;
        if (k[j]) atomicAdd(&hist[(int)(k[j] >> 36) - BINBASE], 1u);
    }
    __syncthreads();

    {   // hierarchical suffix scan over 4096 bins: 8 bins/thread, 16 warps
        const int t8 = tid * 8;
        unsigned h[8], sfx[8];
        #pragma unroll
        for (int i = 0; i < 8; ++i) h[i] = hist[t8 + i];
        sfx[7] = h[7];
        #pragma unroll
        for (int i = 6; i >= 0; --i) sfx[i] = h[i] + sfx[i + 1];
        unsigned gs = sfx[0];
        unsigned suf = gs;
        #pragma unroll
        for (int o = 1; o < 32; o <<= 1) {
            unsigned v = __shfl_down_sync(FULL, suf, o);
            if (lane + o < 32) suf += v;
        }
        if (lane == 0) wsum[wid] = suf;
        __syncthreads();
        if (wid == 0 && lane < 16) {
            unsigned ws = wsum[lane];
            unsigned sw = ws;
            #pragma unroll
            for (int o = 1; o < 16; o <<= 1) {
                unsigned v = __shfl_down_sync(0xffffu, sw, o);
                if (lane + o < 16) sw += v;
            }
            wsufex[lane] = sw - ws;
        }
        __syncthreads();
        unsigned above = wsufex[wid] + (suf - gs);
        #pragma unroll
        for (int i = 0; i < 8; ++i) hist[t8 + i] = sfx[i] + above;
    }
    __syncthreads();

    const int total = (int)hist[0];

    float* out_boxes = out;
    float* out_score = out + (long long)Bn * MAXB * 4;
    float* out_class = out + (long long)Bn * MAXB * 5;

    bool first_chunk = true;

    while (true) {
        __syncthreads();
        int count    = sh_count;
        int consumed = sh_consumed;
        int prevLo   = sh_prevLo;
        if (count >= MAXB || consumed >= total) break;

        if (tid == 0) { sh_binLo = 0; sh_pos = 0; sh_overflow = 0; }
        __syncthreads();

        {   // largest binLo (< prevLo) with >= TARGET unconsumed keys above
            int best = 0;
            for (int t = tid; t < prevLo; t += NTN)
                if ((int)hist[t] - consumed >= TARGET) best = max(best, t);
            best = (int)__reduce_max_sync(FULL, (unsigned)best);
            if (lane == 0 && best) atomicMax(&sh_binLo, best);
        }
        __syncthreads();
        int binLo = sh_binLo;

        // compact keys with bin in [binLo, prevLo) from registers
        #pragma unroll
        for (int j = 0; j < 16; ++j) {
            int bn = (int)(k[j] >> 36) - BINBASE;
            bool take = (k[j] != 0ull) && (bn >= binLo) && (bn < prevLo);
            unsigned msk = __ballot_sync(FULL, take);
            int base = 0;
            if (lane == 0 && msk) base = atomicAdd(&sh_pos, __popc(msk));
            base = __shfl_sync(FULL, base, 0);
            if (take)
                buf[base + __popc(msk & ((1u << lane) - 1u))] = k[j];
        }
        __syncthreads();
        int cnt = sh_pos;
        if (tid == 0) { sh_consumed = consumed + cnt; sh_prevLo = binLo; }
        __syncthreads();

        // rank-sort descending (keys unique): buf -> buf2
        for (int i = tid; i < cnt; i += NTN) {
            unsigned long long ki = buf[i];
            int r = 0;
            for (int j = 0; j < cnt; ++j)
                r += (buf[j] > ki);
            buf2[r] = ki;
        }
        __syncthreads();

        int walk_start = 0;

        if (first_chunk) {
            int M = min(cnt, MCAP);

            if (tid < M) {
                unsigned long long kk = buf2[tid];
                int n = 8191 - (int)((kk >> 8) & 0x1FFFu);
                sbox[tid] = decode_box_(pred, anch, b, n);
            }
            if (tid < MCAP / 32) sbm[tid] = 0u;
            __syncthreads();

            // class-decomposed greedy: 16 warps x 5 classes
            for (int c = wid; c < Cn; c += 16) {
                float4 acc0, acc1;
                int na = 0;
                for (int base = 0; base < M; base += 32) {
                    int i = base + lane;
                    bool mine = (i < M) && ((int)(buf2[i] & 0xFFu) == c);
                    unsigned mk = __ballot_sync(FULL, mine);
                    while (mk) {
                        int i2 = base + (__ffs(mk) - 1);
                        mk &= mk - 1;
                        float4 bx = sbox[i2];
                        bool hit = false;
                        if (lane < na)      hit  = iou_(acc0, bx) > IOU_THR;
                        if (32 + lane < na) hit |= iou_(acc1, bx) > IOU_THR;
                        if (!__any_sync(FULL, hit)) {
                            if (na < 64) {
                                if (lane == (na & 31)) {
                                    if (na < 32) acc0 = bx; else acc1 = bx;
                                }
                                if (lane == 0)
                                    atomicOr(&sbm[i2 >> 5], 1u << (i2 & 31));
                            } else {
                                if (lane == 0) sh_overflow = 1;
                            }
                            ++na;
                        }
                    }
                }
            }
            __syncthreads();

            if (!sh_overflow) {
                if (tid < 32) {   // ordered survivor compaction
                    int c = 0;
                    for (int w = 0; w < MCAP / 32 && c < MAXB; ++w) {
                        unsigned bits = sbm[w];
                        bool set = (bits >> lane) & 1u;
                        int rank = __popc(bits & ((1u << lane) - 1u));
                        int slot = c + rank;
                        if (set && slot < MAXB) {
                            int i2 = w * 32 + lane;
                            unsigned long long key = buf2[i2];
                            float4 bx = sbox[i2];
                            abox[slot] = bx;
                            acls[slot] = (int)(key & 0xFFu);
                            long long o = (long long)b * MAXB + slot;
                            out_boxes[o * 4 + 0] = bx.x;
                            out_boxes[o * 4 + 1] = bx.y;
                            out_boxes[o * 4 + 2] = bx.z;
                            out_boxes[o * 4 + 3] = bx.w;
                            out_score[o] = __uint_as_float((unsigned)(key >> 21));
                            out_class[o] = (float)(key & 0xFFu);
                        }
                        c = min(c + __popc(bits), MAXB);
                    }
                    if (lane == 0) sh_count = c;
                }
                walk_start = M;
            } else {
                walk_start = 0;
            }
            __syncthreads();
            first_chunk = false;
            if (sh_count >= MAXB || walk_start >= cnt) continue;
        }

        // exact fallback: batched serial walk
        for (int base = walk_start; base < cnt; base += MCAP) {
            __syncthreads();
            if (sh_count >= MAXB) break;
            int mm = min(MCAP, cnt - base);

            if (tid < mm) {
                unsigned long long kk = buf2[base + tid];
                int n = 8191 - (int)((kk >> 8) & 0x1FFFu);
                sbox[tid] = decode_box_(pred, anch, b, n);
            }
            __syncthreads();

            if (tid < 32) {
                int c = sh_count;
                for (int ii = 0; ii < mm && c < MAXB; ++ii) {
                    unsigned long long key = buf2[base + ii];
                    int cls = (int)(key & 0xFFu);
                    float4 bx = sbox[ii];
                    bool rej = false;
                    for (int j = lane; j < c; j += 32) {
                        if (acls[j] == cls && iou_(abox[j], bx) > IOU_THR)
                            rej = true;
                    }
                    if (!__any_sync(FULL, rej)) {
                        if (lane == 0) {
                            abox[c] = bx;
                            acls[c] = cls;
                            long long o = (long long)b * MAXB + c;
                            out_boxes[o * 4 + 0] = bx.x;
                            out_boxes[o * 4 + 1] = bx.y;
                            out_boxes[o * 4 + 2] = bx.z;
                            out_boxes[o * 4 + 3] = bx.w;
                            out_score[o] = __uint_as_float((unsigned)(key >> 21));
                            out_class[o] = (float)cls;
                        }
                        __syncwarp();
                        ++c;
                    }
                }
                if (lane == 0) sh_count = c;
            }
        }
    }
    __syncthreads();

    int cnt = sh_count;
    for (int j = tid; j < MAXB; j += NTN) {
        if (j >= cnt) {
            long long o = (long long)b * MAXB + j;
            out_boxes[o * 4 + 0] = 0.0f;
            out_boxes[o * 4 + 1] = 0.0f;
            out_boxes[o * 4 + 2] = 0.0f;
            out_boxes[o * 4 + 3] = 0.0f;
            out_score[o] = 0.0f;
            out_class[o] = -1.0f;
        }
    }
}

extern "C" void kernel_launch(void* const* d_in, const int* in_sizes, int n_in,
                              void* d_out, int out_size)
{
    const float* pred = (const float*)d_in[0];
    const float* anch = (const float*)d_in[1];
    float* out = (float*)d_out;

    cudaFuncSetAttribute(nms_kernel,
                         cudaFuncAttributeMaxDynamicSharedMemorySize, SMEM_NMS);

    decode_kernel<<<NBOX / 128, 512>>>(pred);
    nms_kernel<<<Bn, NTN, SMEM_NMS>>>(out, pred, anch);
}

// round 16
// speedup vs baseline: 1.1737x; 1.0755x over previous
#include <cuda_runtime.h>
#include <cuda_bf16.h>
#include <cstdint>

// ---------------------------------------------------------------------------
// YOLOv2 decode + greedy per-class NMS (exact sorted-walk equivalence).
// R16: decode becomes a persistent double-buffered TMA pipeline (prefetch
//      tile t+stride while computing tile t). NMS identical to R15-best.
// ---------------------------------------------------------------------------

static constexpr int Bn = 64;
static constexpr int Hn = 40;
static constexpr int Wn = 40;
static constexpr int An = 5;
static constexpr int Cn = 80;
static constexpr int NPB = Hn * Wn * An;      // 8000
static constexpr int NBOX = Bn * NPB;         // 512000
static constexpr int MAXB = 100;
static constexpr int NBIN = 4096;             // fine bins: (key>>36) - (117<<8)
static constexpr int BINBASE = 117 << 8;
static constexpr int TARGET = 128;
static constexpr int MCAP = 512;
static constexpr int NTN = 512;               // nms block size
static constexpr float SCORE_THR = 0.001f;
static constexpr float IOU_THR = 0.5f;

static constexpr int NTILE = NBOX / 128;              // 4000 tiles of 128 boxes
static constexpr unsigned TILE_BYTES = 128 * 85 * 4;  // 43520
static constexpr int DEC_GRID = 304;                  // ~2 CTAs/SM persistent

__device__ unsigned long long g_keys[NBOX];

__device__ __forceinline__ unsigned smem_u32(const void* p) {
    unsigned a;
    asm("{ .reg .u64 t; cvta.to.shared.u64 t, %1; cvt.u32.u64 %0, t; }"
        : "=r"(a) : "l"(p));
    return a;
}

// ---------------------------------------------------------------------------
// Decode: persistent, double-buffered. 512 thr/CTA, 4 threads per box.
// ---------------------------------------------------------------------------
__global__ __launch_bounds__(512, 2) void decode_kernel(
    const float* __restrict__ pred)
{
    extern __shared__ __align__(128) unsigned char dsm[];   // 2 * 43520
    __shared__ __align__(8) unsigned long long mbar[2];

    const int tid = threadIdx.x;
    const unsigned FULL = 0xffffffffu;
    const unsigned mb0 = smem_u32(&mbar[0]);
    const unsigned mb1 = smem_u32(&mbar[1]);

    if (tid == 0) {
        asm volatile("mbarrier.init.shared.b64 [%0], 1;" :: "r"(mb0) : "memory");
        asm volatile("mbarrier.init.shared.b64 [%0], 1;" :: "r"(mb1) : "memory");
    }
    __syncthreads();

    const int stride = gridDim.x;

    // prologue: TMA first tile into buffer 0
    if (tid == 0 && blockIdx.x < NTILE) {
        asm volatile("mbarrier.arrive.expect_tx.shared.b64 _, [%0], %1;"
                     :: "r"(mb0), "r"(TILE_BYTES) : "memory");
        asm volatile(
            "cp.async.bulk.shared::cluster.global.mbarrier::complete_tx::bytes "
            "[%0], [%1], %2, [%3];"
            :: "r"(smem_u32(dsm)),
               "l"((const char*)pred + (long long)blockIdx.x * TILE_BYTES),
               "r"(TILE_BYTES), "r"(mb0) : "memory");
    }

    int it = 0;
    for (int t = blockIdx.x; t < NTILE; t += stride, ++it) {
        const int cur = it & 1;
        const unsigned mbc = cur ? mb1 : mb0;
        const unsigned mbn = cur ? mb0 : mb1;
        const float* s = (const float*)(dsm + (unsigned)cur * TILE_BYTES);

        // prefetch next tile into the other buffer (its readers finished at
        // the __syncthreads ending the previous iteration)
        const int tn = t + stride;
        if (tn < NTILE && tid == 0) {
            asm volatile("mbarrier.arrive.expect_tx.shared.b64 _, [%0], %1;"
                         :: "r"(mbn), "r"(TILE_BYTES) : "memory");
            asm volatile(
                "cp.async.bulk.shared::cluster.global.mbarrier::complete_tx::bytes "
                "[%0], [%1], %2, [%3];"
                :: "r"(smem_u32(dsm) + (unsigned)(cur ^ 1) * TILE_BYTES),
                   "l"((const char*)pred + (long long)tn * TILE_BYTES),
                   "r"(TILE_BYTES), "r"(mbn) : "memory");
        }

        // wait current buffer: buffer `cur` usage index = it>>1, parity = bit0
        {
            const unsigned par = (unsigned)((it >> 1) & 1);
            unsigned done;
            do {
                asm volatile(
                    "{ .reg .pred p; "
                    "mbarrier.try_wait.parity.acquire.cta.shared::cta.b64 p, [%1], %2, 0x989680; "
                    "selp.b32 %0, 1, 0, p; }"
                    : "=r"(done) : "r"(mbc), "r"(par) : "memory");
            } while (!done);
        }

        // ----- compute (identical math to R13/R15 decode) -----
        const int boxl = tid >> 2;
        const int q    = tid & 3;
        const float* p = s + boxl * 85;
        const int jb = 5 + q * 20;

        float bv = p[jb];
        int   bc = jb - 5;
        #pragma unroll 4
        for (int j = jb + 1; j < jb + 20; ++j) {
            float v = p[j];
            if (v > bv) { bv = v; bc = j - 5; }
        }
        #pragma unroll
        for (int o = 1; o <= 2; o <<= 1) {
            float obv = __shfl_xor_sync(FULL, bv, o);
            int   obc = __shfl_xor_sync(FULL, bc, o);
            if (obv > bv || (obv == bv && obc < bc)) { bv = obv; bc = obc; }
        }

        float a0 = 0.f, a1 = 0.f;
        #pragma unroll 4
        for (int j = jb; j < jb + 20; j += 2) {
            a0 += expf(p[j]     - bv);
            a1 += expf(p[j + 1] - bv);
        }
        float se = a0 + a1;
        #pragma unroll
        for (int o = 1; o <= 2; o <<= 1)
            se += __shfl_xor_sync(FULL, se, o);

        if (q == 0) {
            const int box = t * 128 + boxl;
            const int n   = box % NPB;
            float conf  = 1.0f / (1.0f + expf(-p[4]));
            float score = conf / se;

            unsigned long long key = 0ull;
            if (score > SCORE_THR) {
                key = ((unsigned long long)__float_as_uint(score) << 21)
                    | ((unsigned long long)(unsigned)(8191 - n) << 8)
                    | (unsigned long long)(unsigned)bc;
            }
            g_keys[box] = key;
        }
        __syncthreads();   // all reads of buffer `cur` done -> reusable
    }
}

__device__ __forceinline__ float iou_(float4 a, float4 b) {
    float xx1 = fmaxf(a.x, b.x), yy1 = fmaxf(a.y, b.y);
    float xx2 = fminf(a.z, b.z), yy2 = fminf(a.w, b.w);
    float inter = fmaxf(xx2 - xx1, 0.0f) * fmaxf(yy2 - yy1, 0.0f);
    float aa = fmaxf(a.z - a.x, 0.0f) * fmaxf(a.w - a.y, 0.0f);
    float ab = fmaxf(b.z - b.x, 0.0f) * fmaxf(b.w - b.y, 0.0f);
    return inter / (aa + ab - inter + 1e-8f);
}

__device__ __forceinline__ float4 decode_box_(
    const float* __restrict__ pred, const float* __restrict__ anch,
    int b, int n)
{
    const float* pp = pred + ((long long)b * NPB + n) * 85;
    float t0 = pp[0], t1 = pp[1], t2 = pp[2], t3 = pp[3];
    int a  = n % An;
    int hw = n / An;
    float gy = (float)(hw / Wn);
    float gx = (float)(hw % Wn);
    float sx = 1.0f / (1.0f + expf(-t0));
    float sy = 1.0f / (1.0f + expf(-t1));
    float cx = (sx + gx) / 40.0f;
    float cy = (sy + gy) / 40.0f;
    float bw = (expf(t2) * anch[2 * a])     / 40.0f;
    float bh = (expf(t3) * anch[2 * a + 1]) / 40.0f;
    return make_float4(cx - 0.5f * bw, cy - 0.5f * bh,
                       cx + 0.5f * bw, cy + 0.5f * bh);
}

// ---------------------------------------------------------------------------
// NMS (identical to R15-best): 512 threads/CTA.
// dyn smem: buf u64[8192] 64KB | buf2 u64[8192] 64KB | sbox f4[512] 8KB
// ---------------------------------------------------------------------------
static constexpr int SMEM_NMS = 8192 * 8 * 2 + MCAP * 16;   // 136 KB

__global__ __launch_bounds__(NTN, 1) void nms_kernel(
    float* __restrict__ out,
    const float* __restrict__ pred, const float* __restrict__ anch)
{
    extern __shared__ unsigned char smraw[];
    unsigned long long* buf  = (unsigned long long*)smraw;
    unsigned long long* buf2 = buf + 8192;
    float4*             sbox = (float4*)(buf2 + 8192);

    __shared__ unsigned hist[NBIN];
    __shared__ float4 abox[MAXB];
    __shared__ int    acls[MAXB];
    __shared__ unsigned sbm[MCAP / 32];
    __shared__ unsigned wsum[16], wsufex[16];
    __shared__ int    sh_count, sh_pos, sh_binLo, sh_prevLo, sh_consumed;
    __shared__ int    sh_overflow;

    const int b    = blockIdx.x;
    const int tid  = threadIdx.x;
    const int lane = tid & 31;
    const int wid  = tid >> 5;
    const unsigned FULL = 0xffffffffu;

    #pragma unroll
    for (int t = tid; t < NBIN; t += NTN) hist[t] = 0u;
    if (tid == 0) { sh_count = 0; sh_consumed = 0; sh_prevLo = NBIN; }
    __syncthreads();

    unsigned long long k[16];
    #pragma unroll
    for (int j = 0; j < 16; ++j) {
        int idx = tid + j * NTN;
        k[j] = (idx < NPB) ? g_keys[b * NPB + idx] : 0ull;
        if (k[j]) atomicAdd(&hist[(int)(k[j] >> 36) - BINBASE], 1u);
    }
    __syncthreads();

    {   // hierarchical suffix scan over 4096 bins: 8 bins/thread, 16 warps
        const int t8 = tid * 8;
        unsigned h[8], sfx[8];
        #pragma unroll
        for (int i = 0; i < 8; ++i) h[i] = hist[t8 + i];
        sfx[7] = h[7];
        #pragma unroll
        for (int i = 6; i >= 0; --i) sfx[i] = h[i] + sfx[i + 1];
        unsigned gs = sfx[0];
        unsigned suf = gs;
        #pragma unroll
        for (int o = 1; o < 32; o <<= 1) {
            unsigned v = __shfl_down_sync(FULL, suf, o);
            if (lane + o < 32) suf += v;
        }
        if (lane == 0) wsum[wid] = suf;
        __syncthreads();
        if (wid == 0 && lane < 16) {
            unsigned ws = wsum[lane];
            unsigned sw = ws;
            #pragma unroll
            for (int o = 1; o < 16; o <<= 1) {
                unsigned v = __shfl_down_sync(0xffffu, sw, o);
                if (lane + o < 16) sw += v;
            }
            wsufex[lane] = sw - ws;
        }
        __syncthreads();
        unsigned above = wsufex[wid] + (suf - gs);
        #pragma unroll
        for (int i = 0; i < 8; ++i) hist[t8 + i] = sfx[i] + above;
    }
    __syncthreads();

    const int total = (int)hist[0];

    float* out_boxes = out;
    float* out_score = out + (long long)Bn * MAXB * 4;
    float* out_class = out + (long long)Bn * MAXB * 5;

    bool first_chunk = true;

    while (true) {
        __syncthreads();
        int count    = sh_count;
        int consumed = sh_consumed;
        int prevLo   = sh_prevLo;
        if (count >= MAXB || consumed >= total) break;

        if (tid == 0) { sh_binLo = 0; sh_pos = 0; sh_overflow = 0; }
        __syncthreads();

        {
            int best = 0;
            for (int t = tid; t < prevLo; t += NTN)
                if ((int)hist[t] - consumed >= TARGET) best = max(best, t);
            best = (int)__reduce_max_sync(FULL, (unsigned)best);
            if (lane == 0 && best) atomicMax(&sh_binLo, best);
        }
        __syncthreads();
        int binLo = sh_binLo;

        #pragma unroll
        for (int j = 0; j < 16; ++j) {
            int bn = (int)(k[j] >> 36) - BINBASE;
            bool take = (k[j] != 0ull) && (bn >= binLo) && (bn < prevLo);
            unsigned msk = __ballot_sync(FULL, take);
            int base = 0;
            if (lane == 0 && msk) base = atomicAdd(&sh_pos, __popc(msk));
            base = __shfl_sync(FULL, base, 0);
            if (take)
                buf[base + __popc(msk & ((1u << lane) - 1u))] = k[j];
        }
        __syncthreads();
        int cnt = sh_pos;
        if (tid == 0) { sh_consumed = consumed + cnt; sh_prevLo = binLo; }
        __syncthreads();

        for (int i = tid; i < cnt; i += NTN) {
            unsigned long long ki = buf[i];
            int r = 0;
            for (int j = 0; j < cnt; ++j)
                r += (buf[j] > ki);
            buf2[r] = ki;
        }
        __syncthreads();

        int walk_start = 0;

        if (first_chunk) {
            int M = min(cnt, MCAP);

            if (tid < M) {
                unsigned long long kk = buf2[tid];
                int n = 8191 - (int)((kk >> 8) & 0x1FFFu);
                sbox[tid] = decode_box_(pred, anch, b, n);
            }
            if (tid < MCAP / 32) sbm[tid] = 0u;
            __syncthreads();

            for (int c = wid; c < Cn; c += 16) {
                float4 acc0, acc1;
                int na = 0;
                for (int base = 0; base < M; base += 32) {
                    int i = base + lane;
                    bool mine = (i < M) && ((int)(buf2[i] & 0xFFu) == c);
                    unsigned mk = __ballot_sync(FULL, mine);
                    while (mk) {
                        int i2 = base + (__ffs(mk) - 1);
                        mk &= mk - 1;
                        float4 bx = sbox[i2];
                        bool hit = false;
                        if (lane < na)      hit  = iou_(acc0, bx) > IOU_THR;
                        if (32 + lane < na) hit |= iou_(acc1, bx) > IOU_THR;
                        if (!__any_sync(FULL, hit)) {
                            if (na < 64) {
                                if (lane == (na & 31)) {
                                    if (na < 32) acc0 = bx; else acc1 = bx;
                                }
                                if (lane == 0)
                                    atomicOr(&sbm[i2 >> 5], 1u << (i2 & 31));
                            } else {
                                if (lane == 0) sh_overflow = 1;
                            }
                            ++na;
                        }
                    }
                }
            }
            __syncthreads();

            if (!sh_overflow) {
                if (tid < 32) {
                    int c = 0;
                    for (int w = 0; w < MCAP / 32 && c < MAXB; ++w) {
                        unsigned bits = sbm[w];
                        bool set = (bits >> lane) & 1u;
                        int rank = __popc(bits & ((1u << lane) - 1u));
                        int slot = c + rank;
                        if (set && slot < MAXB) {
                            int i2 = w * 32 + lane;
                            unsigned long long key = buf2[i2];
                            float4 bx = sbox[i2];
                            abox[slot] = bx;
                            acls[slot] = (int)(key & 0xFFu);
                            long long o = (long long)b * MAXB + slot;
                            out_boxes[o * 4 + 0] = bx.x;
                            out_boxes[o * 4 + 1] = bx.y;
                            out_boxes[o * 4 + 2] = bx.z;
                            out_boxes[o * 4 + 3] = bx.w;
                            out_score[o] = __uint_as_float((unsigned)(key >> 21));
                            out_class[o] = (float)(key & 0xFFu);
                        }
                        c = min(c + __popc(bits), MAXB);
                    }
                    if (lane == 0) sh_count = c;
                }
                walk_start = M;
            } else {
                walk_start = 0;
            }
            __syncthreads();
            first_chunk = false;
            if (sh_count >= MAXB || walk_start >= cnt) continue;
        }

        for (int base = walk_start; base < cnt; base += MCAP) {
            __syncthreads();
            if (sh_count >= MAXB) break;
            int mm = min(MCAP, cnt - base);

            if (tid < mm) {
                unsigned long long kk = buf2[base + tid];
                int n = 8191 - (int)((kk >> 8) & 0x1FFFu);
                sbox[tid] = decode_box_(pred, anch, b, n);
            }
            __syncthreads();

            if (tid < 32) {
                int c = sh_count;
                for (int ii = 0; ii < mm && c < MAXB; ++ii) {
                    unsigned long long key = buf2[base + ii];
                    int cls = (int)(key & 0xFFu);
                    float4 bx = sbox[ii];
                    bool rej = false;
                    for (int j = lane; j < c; j += 32) {
                        if (acls[j] == cls && iou_(abox[j], bx) > IOU_THR)
                            rej = true;
                    }
                    if (!__any_sync(FULL, rej)) {
                        if (lane == 0) {
                            abox[c] = bx;
                            acls[c] = cls;
                            long long o = (long long)b * MAXB + c;
                            out_boxes[o * 4 + 0] = bx.x;
                            out_boxes[o * 4 + 1] = bx.y;
                            out_boxes[o * 4 + 2] = bx.z;
                            out_boxes[o * 4 + 3] = bx.w;
                            out_score[o] = __uint_as_float((unsigned)(key >> 21));
                            out_class[o] = (float)cls;
                        }
                        __syncwarp();
                        ++c;
                    }
                }
                if (lane == 0) sh_count = c;
            }
        }
    }
    __syncthreads();

    int cnt = sh_count;
    for (int j = tid; j < MAXB; j += NTN) {
        if (j >= cnt) {
            long long o = (long long)b * MAXB + j;
            out_boxes[o * 4 + 0] = 0.0f;
            out_boxes[o * 4 + 1] = 0.0f;
            out_boxes[o * 4 + 2] = 0.0f;
            out_boxes[o * 4 + 3] = 0.0f;
            out_score[o] = 0.0f;
            out_class[o] = -1.0f;
        }
    }
}

extern "C" void kernel_launch(void* const* d_in, const int* in_sizes, int n_in,
                              void* d_out, int out_size)
{
    const float* pred = (const float*)d_in[0];
    const float* anch = (const float*)d_in[1];
    float* out = (float*)d_out;

    cudaFuncSetAttribute(decode_kernel,
                         cudaFuncAttributeMaxDynamicSharedMemorySize,
                         2 * (int)TILE_BYTES);
    cudaFuncSetAttribute(nms_kernel,
                         cudaFuncAttributeMaxDynamicSharedMemorySize, SMEM_NMS);

    decode_kernel<<<DEC_GRID, 512, 2 * TILE_BYTES>>>(pred);
    nms_kernel<<<Bn, NTN, SMEM_NMS>>>(out, pred, anch);
}